// round 7
// baseline (speedup 1.0000x reference)
#include <cuda_runtime.h>

// Problem constants
#define SN 4096
#define HN 1024
#define BN 4
#define RN 16
#define ROWS_TOT (BN * SN)     // 16384

// k1 tiling
#define KQ4 4                  // split-K factor
#define KQLEN (HN / KQ4)       // 256 k per split
#define KC 32                  // k per chunk
#define NCH (KQLEN / KC)       // 8 chunks
#define BM 256                 // rows per CTA
#define PTA 36                 // A pitch (floats): 4-way max, 16B rows
#define PTW 36                 // W pitch
#define SMEM_K1 ((2*BM*PTA + 2*32*PTW + KQLEN) * 4)   // 83968 B

// ---------------- scratch (device globals; no allocation) ----------------
__device__ float g_part[KQ4 * 33 * ROWS_TOT];  // split-K partials [kq][j][row]
__device__ float g_Pp[BN * SN * RN];           // plain P [b][s][r]
__device__ float g_Ur[BN * 8 * SN * 2];        // U r-pair interleaved [b][rp][t][2]
__device__ float g_V[BN * SN];                 // bias-term dot [b][t]

// packed f32x2 FMA (SASS FFMA2, dual-rate)
__device__ __forceinline__ float2 ffma2(float2 a, float2 b, float2 c) {
    float2 d;
    asm("fma.rn.f32x2 %0, %1, %2, %3;"
        : "=l"(*reinterpret_cast<unsigned long long*>(&d))
        : "l"(*reinterpret_cast<unsigned long long*>(&a)),
          "l"(*reinterpret_cast<unsigned long long*>(&b)),
          "l"(*reinterpret_cast<unsigned long long*>(&c)));
    return d;
}

__device__ __forceinline__ void cp16(void* smem_dst, const void* gmem_src) {
    unsigned sdst = (unsigned)__cvta_generic_to_shared(smem_dst);
    asm volatile("cp.async.cg.shared.global [%0], [%1], 16;"
                 :: "r"(sdst), "l"(gmem_src) : "memory");
}
__device__ __forceinline__ void cp_commit() {
    asm volatile("cp.async.commit_group;" ::: "memory");
}
__device__ __forceinline__ void cp_wait0() {
    asm volatile("cp.async.wait_group 0;" ::: "memory");
}

// =======================================================================
// kernel 1: split-K projection partials. grid (64, 4), 256 thr, occ 2.
//   Warp tile m=4 x n=8: per q-step 4 per-lane a-LDS.128 + 8 uniform
//   w-LDS.128 + 64 FFMA2. All 256 CTAs resident in one wave.
// =======================================================================
__global__ __launch_bounds__(256, 2)
void k1_proj(const float* __restrict__ hs,
             const float* __restrict__ wc,
             const float* __restrict__ we,
             const float* __restrict__ be) {
    extern __shared__ float smem[];
    float* As = smem;                        // [2][BM*PTA]
    float* Ws = smem + 2 * BM * PTA;         // [2][32*PTW]
    float* bes = Ws + 2 * 32 * PTW;          // [KQLEN]

    const int tid = threadIdx.x;
    const int x = tid & 31;
    const int wid = tid >> 5;
    const int rh = wid & 1;
    const int g = wid >> 1;                  // n-group 0..3
    const int r0 = x + 32 * rh;              // base row; +64*m
    const int rowBase = blockIdx.x * BM;
    const int kq = blockIdx.y;
    const int kOff = kq * KQLEN;

    // besum slice for this k-quarter (1 col per thread, coalesced per rule)
    {
        float s = 0.f;
        #pragma unroll
        for (int r = 0; r < RN; r++) s += be[r * HN + kOff + tid];
        bes[tid] = s;
    }

    auto stage = [&](int c, int buf) {
        // A: 256 rows x 32 k = 2048 float4, 8 per thread
        #pragma unroll
        for (int i = 0; i < 8; i++) {
            int idx = tid + 256 * i;
            int row = idx >> 3, k4 = idx & 7;
            cp16(&As[buf * BM * PTA + row * PTA + k4 * 4],
                 &hs[(size_t)(rowBase + row) * HN + kOff + c * KC + k4 * 4]);
        }
        // W: 32 n x 32 k = 256 float4, 1 per thread
        {
            int n = tid >> 3, k4 = tid & 7;
            const float* src = (n < 16)
                ? &wc[n * HN + kOff + c * KC + k4 * 4]
                : &we[(n - 16) * HN + kOff + c * KC + k4 * 4];
            cp16(&Ws[buf * 32 * PTW + n * PTW + k4 * 4], src);
        }
        cp_commit();
    };

    float2 acc[4][8];
    #pragma unroll
    for (int m = 0; m < 4; m++)
        #pragma unroll
        for (int n = 0; n < 8; n++) acc[m][n] = make_float2(0.f, 0.f);
    float2 vacc[4];
    #pragma unroll
    for (int m = 0; m < 4; m++) vacc[m] = make_float2(0.f, 0.f);

    stage(0, 0);

    for (int c = 0; c < NCH; c++) {
        cp_wait0();
        __syncthreads();
        if (c + 1 < NCH) stage(c + 1, (c + 1) & 1);
        const int buf = c & 1;
        const float4* As4 = reinterpret_cast<const float4*>(&As[buf * BM * PTA]);
        const float4* Ws4 = reinterpret_cast<const float4*>(&Ws[buf * 32 * PTW]);
        const float4* bs4 = reinterpret_cast<const float4*>(&bes[c * KC]);

        #pragma unroll
        for (int q = 0; q < 8; q++) {
            float4 w4[8];
            #pragma unroll
            for (int n = 0; n < 8; n++)
                w4[n] = Ws4[(g * 8 + n) * (PTW / 4) + q];   // uniform
            float4 b4;
            if (g == 0) b4 = bs4[q];                        // uniform

            #pragma unroll
            for (int m = 0; m < 4; m++) {
                float4 a4 = As4[(r0 + 64 * m) * (PTA / 4) + q];
                float2 alo = make_float2(a4.x, a4.y);
                float2 ahi = make_float2(a4.z, a4.w);
                #pragma unroll
                for (int n = 0; n < 8; n++) {
                    acc[m][n] = ffma2(alo, make_float2(w4[n].x, w4[n].y), acc[m][n]);
                    acc[m][n] = ffma2(ahi, make_float2(w4[n].z, w4[n].w), acc[m][n]);
                }
                if (g == 0) {
                    vacc[m] = ffma2(alo, make_float2(b4.x, b4.y), vacc[m]);
                    vacc[m] = ffma2(ahi, make_float2(b4.z, b4.w), vacc[m]);
                }
            }
        }
        __syncthreads();
    }

    // write partials (coalesced: 32 consecutive rows per warp)
    #pragma unroll
    for (int m = 0; m < 4; m++) {
        int row = rowBase + r0 + 64 * m;
        #pragma unroll
        for (int n = 0; n < 8; n++) {
            int j = g * 8 + n;
            g_part[(kq * 33 + j) * ROWS_TOT + row] = acc[m][n].x + acc[m][n].y;
        }
        if (g == 0)
            g_part[(kq * 33 + 32) * ROWS_TOT + row] = vacc[m].x + vacc[m].y;
    }
}

// =======================================================================
// k1_reduce: sum 4 split-K partials, epilogue, scatter to P / Ur / V.
// =======================================================================
__global__ __launch_bounds__(256)
void k1_reduce(const float* __restrict__ bc,
               const float* __restrict__ strength) {
    const int row = blockIdx.x * 256 + threadIdx.x;
    const int j = blockIdx.y;
    float v = 0.f;
    #pragma unroll
    for (int kq = 0; kq < KQ4; kq++)
        v += g_part[(kq * 33 + j) * ROWS_TOT + row];
    const int b = row >> 12;
    const int s = row & (SN - 1);
    if (j < 16) {
        g_Pp[(b * SN + s) * RN + j] = (v + bc[j]) * strength[j];
    } else if (j < 32) {
        int r = j - 16;
        g_Ur[(((b * 8) + (r >> 1)) * SN + s) * 2 + (r & 1)] = v;
    } else {
        g_V[b * SN + s] = v;
    }
}

// =======================================================================
// kernel 2: bias[b,s,t] = sum_r P[b,s,r]*U[b,r,t] + V[b,t]
//   Rule-pair packing: acc2 += (p2r,p2r+1)*(u2r[t],u2r+1[t]); final x+y+V.
//   Per s-step: 4 uniform LDS.128 (P) + 32 FFMA2 + 4 FADD + 1 STG.128.
// =======================================================================
#define K2_TB 1024
#define K2_SB 64

__global__ __launch_bounds__(256, 2)
void k2_outer(float* __restrict__ out) {
    __shared__ __align__(16) float4 Ps[K2_SB * 4];   // 64 s x 16 floats = 4KB

    const int tid = threadIdx.x;
    const int w = tid >> 5;
    const int l = tid & 31;
    const int b = blockIdx.z;
    const int sB = blockIdx.y * K2_SB;
    const int t = blockIdx.x * K2_TB + w * 128 + l * 4;

    // stage P tile: exactly 256 float4
    Ps[tid] = reinterpret_cast<const float4*>(&g_Pp[(b * SN + sB) * RN])[tid];

    // U r-pairs for my 4 t: u2[rp][j] = (U[2rp][t+j], U[2rp+1][t+j])
    float2 u2[8][4];
    #pragma unroll
    for (int rp = 0; rp < 8; rp++) {
        const float4* ub = reinterpret_cast<const float4*>(
            &g_Ur[((size_t)(b * 8 + rp) * SN + t) * 2]);
        float4 lo = ub[0], hi = ub[1];
        u2[rp][0] = make_float2(lo.x, lo.y);
        u2[rp][1] = make_float2(lo.z, lo.w);
        u2[rp][2] = make_float2(hi.x, hi.y);
        u2[rp][3] = make_float2(hi.z, hi.w);
    }

    float4 v4 = *reinterpret_cast<const float4*>(&g_V[b * SN + t]);

    __syncthreads();

    float* orow = out + (size_t)(b * SN + sB) * SN + t;

    #pragma unroll 2
    for (int si = 0; si < K2_SB; si++) {
        float4 q0 = Ps[si * 4 + 0], q1 = Ps[si * 4 + 1];
        float4 q2 = Ps[si * 4 + 2], q3 = Ps[si * 4 + 3];
        float2 p2[8] = {
            make_float2(q0.x, q0.y), make_float2(q0.z, q0.w),
            make_float2(q1.x, q1.y), make_float2(q1.z, q1.w),
            make_float2(q2.x, q2.y), make_float2(q2.z, q2.w),
            make_float2(q3.x, q3.y), make_float2(q3.z, q3.w)
        };

        float2 a0 = make_float2(v4.x, 0.f), a1 = make_float2(v4.y, 0.f);
        float2 a2 = make_float2(v4.z, 0.f), a3 = make_float2(v4.w, 0.f);
        #pragma unroll
        for (int rp = 0; rp < 8; rp++) {
            a0 = ffma2(p2[rp], u2[rp][0], a0);
            a1 = ffma2(p2[rp], u2[rp][1], a1);
            a2 = ffma2(p2[rp], u2[rp][2], a2);
            a3 = ffma2(p2[rp], u2[rp][3], a3);
        }

        __stcs(reinterpret_cast<float4*>(orow + (size_t)si * SN),
               make_float4(a0.x + a0.y, a1.x + a1.y, a2.x + a2.y, a3.x + a3.y));
    }
}

// ---------------- launch ----------------
extern "C" void kernel_launch(void* const* d_in, const int* in_sizes, int n_in,
                              void* d_out, int out_size) {
    const float* hs       = (const float*)d_in[0];
    const float* wc       = (const float*)d_in[1];
    const float* bc       = (const float*)d_in[2];
    const float* we       = (const float*)d_in[3];
    const float* be       = (const float*)d_in[4];
    const float* strength = (const float*)d_in[5];
    float* out = (float*)d_out;

    cudaFuncSetAttribute(k1_proj,
                         cudaFuncAttributeMaxDynamicSharedMemorySize, SMEM_K1);
    k1_proj<<<dim3(ROWS_TOT / BM, KQ4), 256, SMEM_K1>>>(hs, wc, we, be);
    k1_reduce<<<dim3(ROWS_TOT / 256, 33), 256>>>(bc, strength);
    k2_outer<<<dim3(SN / K2_TB, SN / K2_SB, BN), 256>>>(out);
}